// round 11
// baseline (speedup 1.0000x reference)
#include <cuda_runtime.h>
#include <cuda_fp16.h>
#include <math.h>

#define N_NODES 50000
#define N_EDGES 800000
#define FEAT    128
#define SCAN_BLOCKS 196   // ceil(50000/256)

// Scratch (device globals; no allocation allowed in kernel_launch).
__device__ float g_w[N_NODES];                        // w = exp(x @ a)
__device__ int   g_cnt[N_NODES];                      // degree (re-zeroed by scanA)
__device__ int   g_rowptr[N_NODES + 1];               // CSR row pointers
__device__ int   g_blocksum[SCAN_BLOCKS];             // scan partials
__device__ __align__(16) int  g_rank[N_EDGES];        // edge rank within its row
__device__ __align__(16) int2 g_pair[N_EDGES];        // {cidx, w bits} in CSR order
__device__ __align__(16) __half g_xh[N_NODES * FEAT]; // fp16 copy of x

// K1: fused — w[i] = exp(dot(x[i,:], a)) (warp per node), fp16 copy of x,
// degree histogram + per-edge rank capture (thread per edge).
__global__ void k_score(const float* __restrict__ x, const float* __restrict__ a,
                        const int* __restrict__ row) {
    __shared__ float sa[FEAT];
    int tid = threadIdx.x;
    if (tid < FEAT) sa[tid] = a[tid];
    __syncthreads();
    int gt = blockIdx.x * blockDim.x + tid;

    // histogram + rank (the atomic's return value IS the rank)
    if (gt < N_EDGES) g_rank[gt] = atomicAdd(&g_cnt[row[gt]], 1);

    int gwarp = gt >> 5;
    int lane = tid & 31;
    if (gwarp >= N_NODES) return;
    float4 v = ((const float4*)x)[gwarp * 32 + lane];

    __half2 p0 = __floats2half2_rn(v.x, v.y);
    __half2 p1 = __floats2half2_rn(v.z, v.w);
    uint2 packed;
    packed.x = *(unsigned int*)&p0;
    packed.y = *(unsigned int*)&p1;
    ((uint2*)g_xh)[gwarp * 32 + lane] = packed;

    float4 w = ((const float4*)sa)[lane];
    float s = v.x * w.x + v.y * w.y + v.z * w.z + v.w * w.w;
    #pragma unroll
    for (int o = 16; o; o >>= 1) s += __shfl_xor_sync(0xffffffffu, s, o);
    if (lane == 0) g_w[gwarp] = expf(s);   // e ~ N(0, sqrt(2)) -> exp safe in fp32
}

// K2a: per-block exclusive scan of g_cnt -> g_rowptr (local), totals -> g_blocksum.
// Re-zeroes g_cnt for the next graph replay.
__global__ void k_scanA() {
    int i = blockIdx.x * 256 + threadIdx.x;
    int v = 0;
    if (i < N_NODES) { v = g_cnt[i]; g_cnt[i] = 0; }
    int lane = threadIdx.x & 31, w = threadIdx.x >> 5;
    int s = v;
    #pragma unroll
    for (int o = 1; o < 32; o <<= 1) {
        int t = __shfl_up_sync(0xffffffffu, s, o);
        if (lane >= o) s += t;
    }
    __shared__ int ws[8];
    if (lane == 31) ws[w] = s;
    __syncthreads();
    if (w == 0) {
        int t = (lane < 8) ? ws[lane] : 0;
        #pragma unroll
        for (int o = 1; o < 8; o <<= 1) {
            int u = __shfl_up_sync(0xffffffffu, t, o);
            if (lane >= o) t += u;
        }
        if (lane < 8) ws[lane] = t;
    }
    __syncthreads();
    int excl = s - v + (w > 0 ? ws[w - 1] : 0);
    if (i < N_NODES) g_rowptr[i] = excl;
    if (threadIdx.x == 0) g_blocksum[blockIdx.x] = ws[7];
}

// K2b: each block computes its prefix over g_blocksum by block-reduce,
// adds it to its rowptr slice.
__global__ void k_scanB() {
    int tid = threadIdx.x;
    int v = (tid < SCAN_BLOCKS && tid < blockIdx.x) ? g_blocksum[tid] : 0;
    int lane = tid & 31, w = tid >> 5;
    #pragma unroll
    for (int o = 16; o; o >>= 1) v += __shfl_xor_sync(0xffffffffu, v, o);
    __shared__ int ws[8];
    if (lane == 0) ws[w] = v;
    __syncthreads();
    if (tid == 0) {
        int t = 0;
        #pragma unroll
        for (int j = 0; j < 8; j++) t += ws[j];
        ws[0] = t;
    }
    __syncthreads();
    int prefix = ws[0];

    int i = blockIdx.x * 256 + tid;
    if (i < N_NODES) g_rowptr[i] += prefix;
    if (i == 0) g_rowptr[N_NODES] = N_EDGES;
}

// K3: counting-sort fill — NO atomics, 4 edges per thread.
// Phase 1: three int4 loads (row/col/rank). Phase 2: 8 independent 4B gathers.
// Phase 3: 4 independent 8B paired stores. MLP ~8 on the gather phase.
__global__ void k_fill(const int* __restrict__ row, const int* __restrict__ col) {
    int t = blockIdx.x * blockDim.x + threadIdx.x;   // N_EDGES/4 threads
    if (t >= N_EDGES / 4) return;
    int4 r4 = ((const int4*)row)[t];
    int4 c4 = ((const int4*)col)[t];
    int4 k4 = ((const int4*)g_rank)[t];

    int rp0 = g_rowptr[r4.x];
    int rp1 = g_rowptr[r4.y];
    int rp2 = g_rowptr[r4.z];
    int rp3 = g_rowptr[r4.w];
    float w0 = g_w[c4.x];
    float w1 = g_w[c4.y];
    float w2 = g_w[c4.z];
    float w3 = g_w[c4.w];

    g_pair[rp0 + k4.x] = make_int2(c4.x, __float_as_int(w0));
    g_pair[rp1 + k4.y] = make_int2(c4.y, __float_as_int(w1));
    g_pair[rp2 + k4.z] = make_int2(c4.z, __float_as_int(w2));
    g_pair[rp3 + k4.w] = make_int2(c4.w, __float_as_int(w3));
}

// K4: warp per row, HALF-WARP per edge. Each half-warp (16 lanes x 16B uint4)
// covers the full 256B fp16 feature row of one edge; the two halves take
// alternate edges. Combine via shfl_down(16); lanes 0..15 store 2x float4.
__global__ void k_row(float* __restrict__ h) {
    int gw = (blockIdx.x * blockDim.x + threadIdx.x) >> 5;
    int lane = threadIdx.x & 31;
    if (gw >= N_NODES) return;
    int s0 = g_rowptr[gw], s1 = g_rowptr[gw + 1];

    int half = lane >> 4;        // 0 or 1
    int hl   = lane & 15;        // lane within half-warp

    const uint4* xh = (const uint4*)g_xh;   // 16B = 8 halves per lane
    float acc[8] = {0.f, 0.f, 0.f, 0.f, 0.f, 0.f, 0.f, 0.f};
    float wsum = 0.0f;

    for (int i = s0 + half; i < s1; i += 2) {
        int2 pr = g_pair[i];                 // 8B broadcast within half-warp
        float wgt = __int_as_float(pr.y);
        wsum += wgt;
        uint4 p = xh[pr.x * 16 + hl];        // one LDG.128 per lane per edge
        float2 f0 = __half22float2(*(__half2*)&p.x);
        float2 f1 = __half22float2(*(__half2*)&p.y);
        float2 f2 = __half22float2(*(__half2*)&p.z);
        float2 f3 = __half22float2(*(__half2*)&p.w);
        acc[0] += wgt * f0.x;  acc[1] += wgt * f0.y;
        acc[2] += wgt * f1.x;  acc[3] += wgt * f1.y;
        acc[4] += wgt * f2.x;  acc[5] += wgt * f2.y;
        acc[6] += wgt * f3.x;  acc[7] += wgt * f3.y;
    }

    // combine the two half-warps (lane i += lane i+16)
    #pragma unroll
    for (int j = 0; j < 8; j++)
        acc[j] += __shfl_down_sync(0xffffffffu, acc[j], 16);
    wsum += __shfl_down_sync(0xffffffffu, wsum, 16);

    if (half == 0) {
        float inv = (s1 > s0) ? 1.0f / wsum : 0.0f;
        float4 o0 = make_float4(acc[0] * inv, acc[1] * inv, acc[2] * inv, acc[3] * inv);
        float4 o1 = make_float4(acc[4] * inv, acc[5] * inv, acc[6] * inv, acc[7] * inv);
        float4* dst = (float4*)(h + (size_t)gw * FEAT + hl * 8);
        dst[0] = o0;
        dst[1] = o1;
    }
}

extern "C" void kernel_launch(void* const* d_in, const int* in_sizes, int n_in,
                              void* d_out, int out_size) {
    const float* x   = (const float*)d_in[0];  // [N_NODES, FEAT]
    const float* a   = (const float*)d_in[1];  // [FEAT, 1]
    const int*   row = (const int*)d_in[2];    // [N_EDGES] int32
    const int*   col = (const int*)d_in[3];    // [N_EDGES] int32
    float* h = (float*)d_out;                  // [N_NODES, FEAT]

    int score_blocks = (N_NODES * 32 + 255) / 256;   // warp/node + thread/edge
    k_score<<<score_blocks, 256>>>(x, a, row);

    k_scanA<<<SCAN_BLOCKS, 256>>>();
    k_scanB<<<SCAN_BLOCKS, 256>>>();

    int fill_blocks = (N_EDGES / 4 + 255) / 256;     // 4 edges per thread
    k_fill<<<fill_blocks, 256>>>(row, col);

    int row_blocks = (N_NODES * 32 + 255) / 256;     // warp per row
    k_row<<<row_blocks, 256>>>(h);
}

// round 12
// speedup vs baseline: 1.1387x; 1.1387x over previous
#include <cuda_runtime.h>
#include <cuda_fp16.h>
#include <math.h>

#define N_NODES 50000
#define N_EDGES 800000
#define FEAT    128
#define SCAN_BLOCKS 196   // ceil(50000/256)

// Scratch (device globals; no allocation allowed in kernel_launch).
__device__ float g_w[N_NODES];                        // w = exp(x @ a)
__device__ int   g_cnt[N_NODES];                      // degree (re-zeroed by scanA)
__device__ int   g_rowptr[N_NODES + 1];               // CSR row pointers
__device__ int   g_blocksum[SCAN_BLOCKS];             // scan partials
__device__ __align__(16) int g_rank[N_EDGES];         // edge rank within its row
__device__ __align__(16) int g_cidx[N_EDGES];         // CSR column indices
__device__ __align__(16) __half g_xh[N_NODES * FEAT]; // fp16 copy of x

// K1: fused — w[i] = exp(dot(x[i,:], a)) (warp per node), fp16 copy of x,
// degree histogram + per-edge rank capture (thread per edge).
__global__ void k_score(const float* __restrict__ x, const float* __restrict__ a,
                        const int* __restrict__ row) {
    __shared__ float sa[FEAT];
    int tid = threadIdx.x;
    if (tid < FEAT) sa[tid] = a[tid];
    __syncthreads();
    int gt = blockIdx.x * blockDim.x + tid;

    // histogram + rank (the atomic's return value IS the rank)
    if (gt < N_EDGES) g_rank[gt] = atomicAdd(&g_cnt[row[gt]], 1);

    int gwarp = gt >> 5;
    int lane = tid & 31;
    if (gwarp >= N_NODES) return;
    float4 v = ((const float4*)x)[gwarp * 32 + lane];

    __half2 p0 = __floats2half2_rn(v.x, v.y);
    __half2 p1 = __floats2half2_rn(v.z, v.w);
    uint2 packed;
    packed.x = *(unsigned int*)&p0;
    packed.y = *(unsigned int*)&p1;
    ((uint2*)g_xh)[gwarp * 32 + lane] = packed;

    float4 w = ((const float4*)sa)[lane];
    float s = v.x * w.x + v.y * w.y + v.z * w.z + v.w * w.w;
    #pragma unroll
    for (int o = 16; o; o >>= 1) s += __shfl_xor_sync(0xffffffffu, s, o);
    if (lane == 0) g_w[gwarp] = expf(s);   // e ~ N(0, sqrt(2)) -> exp safe in fp32
}

// K2a: per-block exclusive scan of g_cnt -> g_rowptr (local), totals -> g_blocksum.
// Re-zeroes g_cnt for the next graph replay.
__global__ void k_scanA() {
    int i = blockIdx.x * 256 + threadIdx.x;
    int v = 0;
    if (i < N_NODES) { v = g_cnt[i]; g_cnt[i] = 0; }
    int lane = threadIdx.x & 31, w = threadIdx.x >> 5;
    int s = v;
    #pragma unroll
    for (int o = 1; o < 32; o <<= 1) {
        int t = __shfl_up_sync(0xffffffffu, s, o);
        if (lane >= o) s += t;
    }
    __shared__ int ws[8];
    if (lane == 31) ws[w] = s;
    __syncthreads();
    if (w == 0) {
        int t = (lane < 8) ? ws[lane] : 0;
        #pragma unroll
        for (int o = 1; o < 8; o <<= 1) {
            int u = __shfl_up_sync(0xffffffffu, t, o);
            if (lane >= o) t += u;
        }
        if (lane < 8) ws[lane] = t;
    }
    __syncthreads();
    int excl = s - v + (w > 0 ? ws[w - 1] : 0);
    if (i < N_NODES) g_rowptr[i] = excl;
    if (threadIdx.x == 0) g_blocksum[blockIdx.x] = ws[7];
}

// K2b: each block computes its prefix over g_blocksum by block-reduce,
// adds it to its rowptr slice.
__global__ void k_scanB() {
    int tid = threadIdx.x;
    int v = (tid < SCAN_BLOCKS && tid < blockIdx.x) ? g_blocksum[tid] : 0;
    int lane = tid & 31, w = tid >> 5;
    #pragma unroll
    for (int o = 16; o; o >>= 1) v += __shfl_xor_sync(0xffffffffu, v, o);
    __shared__ int ws[8];
    if (lane == 0) ws[w] = v;
    __syncthreads();
    if (tid == 0) {
        int t = 0;
        #pragma unroll
        for (int j = 0; j < 8; j++) t += ws[j];
        ws[0] = t;
    }
    __syncthreads();
    int prefix = ws[0];

    int i = blockIdx.x * 256 + tid;
    if (i < N_NODES) g_rowptr[i] += prefix;
    if (i == 0) g_rowptr[N_NODES] = N_EDGES;
}

// K3: counting-sort fill — NO atomics, NO w gather. Per edge: one rowptr
// gather + one 4B cidx scatter (2 divergent accesses, was 3). 2 edges/thread.
__global__ void k_fill(const int* __restrict__ row, const int* __restrict__ col) {
    int t = blockIdx.x * blockDim.x + threadIdx.x;   // N_EDGES/2 threads
    if (t >= N_EDGES / 2) return;
    int2 r2 = ((const int2*)row)[t];
    int2 c2 = ((const int2*)col)[t];
    int2 k2 = ((const int2*)g_rank)[t];

    int p0 = g_rowptr[r2.x] + k2.x;
    int p1 = g_rowptr[r2.y] + k2.y;

    g_cidx[p0] = c2.x;
    g_cidx[p1] = c2.y;
}

// K4: warp per row, HALF-WARP per edge. Per edge: cidx broadcast load,
// g_w[c] broadcast gather (L1-friendly, 200KB array), one LDG.128 per lane
// for the 256B fp16 feature row. Combine via shfl_down(16).
__global__ void k_row(float* __restrict__ h) {
    int gw = (blockIdx.x * blockDim.x + threadIdx.x) >> 5;
    int lane = threadIdx.x & 31;
    if (gw >= N_NODES) return;
    int s0 = g_rowptr[gw], s1 = g_rowptr[gw + 1];

    int half = lane >> 4;        // 0 or 1
    int hl   = lane & 15;        // lane within half-warp

    const uint4* xh = (const uint4*)g_xh;   // 16B = 8 halves per lane
    float acc[8] = {0.f, 0.f, 0.f, 0.f, 0.f, 0.f, 0.f, 0.f};
    float wsum = 0.0f;

    for (int i = s0 + half; i < s1; i += 2) {
        int c = __ldg(&g_cidx[i]);           // broadcast within half-warp
        float wgt = __ldg(&g_w[c]);          // broadcast gather (hot in L1/L2)
        wsum += wgt;
        uint4 p = xh[c * 16 + hl];           // one LDG.128 per lane per edge
        float2 f0 = __half22float2(*(__half2*)&p.x);
        float2 f1 = __half22float2(*(__half2*)&p.y);
        float2 f2 = __half22float2(*(__half2*)&p.z);
        float2 f3 = __half22float2(*(__half2*)&p.w);
        acc[0] += wgt * f0.x;  acc[1] += wgt * f0.y;
        acc[2] += wgt * f1.x;  acc[3] += wgt * f1.y;
        acc[4] += wgt * f2.x;  acc[5] += wgt * f2.y;
        acc[6] += wgt * f3.x;  acc[7] += wgt * f3.y;
    }

    // combine the two half-warps (lane i += lane i+16)
    #pragma unroll
    for (int j = 0; j < 8; j++)
        acc[j] += __shfl_down_sync(0xffffffffu, acc[j], 16);
    wsum += __shfl_down_sync(0xffffffffu, wsum, 16);

    if (half == 0) {
        float inv = (s1 > s0) ? 1.0f / wsum : 0.0f;
        float4 o0 = make_float4(acc[0] * inv, acc[1] * inv, acc[2] * inv, acc[3] * inv);
        float4 o1 = make_float4(acc[4] * inv, acc[5] * inv, acc[6] * inv, acc[7] * inv);
        float4* dst = (float4*)(h + (size_t)gw * FEAT + hl * 8);
        dst[0] = o0;
        dst[1] = o1;
    }
}

extern "C" void kernel_launch(void* const* d_in, const int* in_sizes, int n_in,
                              void* d_out, int out_size) {
    const float* x   = (const float*)d_in[0];  // [N_NODES, FEAT]
    const float* a   = (const float*)d_in[1];  // [FEAT, 1]
    const int*   row = (const int*)d_in[2];    // [N_EDGES] int32
    const int*   col = (const int*)d_in[3];    // [N_EDGES] int32
    float* h = (float*)d_out;                  // [N_NODES, FEAT]

    int score_blocks = (N_NODES * 32 + 255) / 256;   // warp/node + thread/edge
    k_score<<<score_blocks, 256>>>(x, a, row);

    k_scanA<<<SCAN_BLOCKS, 256>>>();
    k_scanB<<<SCAN_BLOCKS, 256>>>();

    int fill_blocks = (N_EDGES / 2 + 255) / 256;     // 2 edges per thread
    k_fill<<<fill_blocks, 256>>>(row, col);

    int row_blocks = (N_NODES * 32 + 255) / 256;     // warp per row
    k_row<<<row_blocks, 256>>>(h);
}